// round 13
// baseline (speedup 1.0000x reference)
#include <cuda_runtime.h>
#include <cuda_fp16.h>
#include <cstdint>

#define B_ 4
#define T_ 256
#define U_ 64
#define D_ 512
#define H_ 512
#define V_ 1024

// ---------------------------------------------------------------------------
// Device-global scratch (allocation-free rule)
// ---------------------------------------------------------------------------
__device__ float g_enc[B_ * T_ * H_];          // 1024 x 512 enc_proj (fp32)
__device__ float g_dec[B_ * U_ * H_];          // 256  x 512 dec_proj + b1 (fp32)
__device__ uint4 g_w2p[4 * 16 * 1024];         // w2 fp16 frag-packed (1 MB)

__device__ __forceinline__ uint32_t f2tf32(float x) {
    uint32_t u; asm("cvt.rna.tf32.f32 %0, %1;" : "=r"(u) : "f"(x)); return u;
}
__device__ __forceinline__ uint32_t packh2(float a, float b) {
    __half2 h = __floats2half2_rn(a, b);
    return *reinterpret_cast<uint32_t*>(&h);
}
__device__ __forceinline__ float gelu_tanh(float x) {
    float t = 0.7978845608028654f * (x + 0.044715f * x * x * x);
    float th; asm("tanh.approx.f32 %0, %1;" : "=f"(th) : "f"(t));
    return 0.5f * x * (1.0f + th);
}
__device__ __forceinline__ uint32_t smem_u32(const void* p) {
    uint32_t a;
    asm("{ .reg .u64 t; cvta.to.shared.u64 t, %1; cvt.u32.u64 %0, t; }" : "=r"(a) : "l"(p));
    return a;
}
__device__ __forceinline__ void mma_tf32(float* acc, uint32_t a0, uint32_t a1,
                                         uint32_t a2, uint32_t a3,
                                         uint32_t b0, uint32_t b1) {
    asm volatile(
        "mma.sync.aligned.m16n8k8.row.col.f32.tf32.tf32.f32 "
        "{%0,%1,%2,%3}, {%4,%5,%6,%7}, {%8,%9}, {%0,%1,%2,%3};"
        : "+f"(acc[0]), "+f"(acc[1]), "+f"(acc[2]), "+f"(acc[3])
        : "r"(a0), "r"(a1), "r"(a2), "r"(a3), "r"(b0), "r"(b1));
}
// f16-accumulate HMMA: D,C are f16x2 pairs (double rate vs f32 acc)
__device__ __forceinline__ void mma_f16h(uint32_t* d, uint32_t a0, uint32_t a1,
                                         uint32_t a2, uint32_t a3,
                                         uint32_t b0, uint32_t b1) {
    asm volatile(
        "mma.sync.aligned.m16n8k16.row.col.f16.f16.f16.f16 "
        "{%0,%1}, {%2,%3,%4,%5}, {%6,%7}, {%0,%1};"
        : "+r"(d[0]), "+r"(d[1])
        : "r"(a0), "r"(a1), "r"(a2), "r"(a3), "r"(b0), "r"(b1));
}
__device__ __forceinline__ void cp16(uint32_t sdst, const void* gsrc) {
    asm volatile("cp.async.cg.shared.global [%0], [%1], 16;" :: "r"(sdst), "l"(gsrc));
}
__device__ __forceinline__ void cp_commit() {
    asm volatile("cp.async.commit_group;" ::: "memory");
}
template <int N>
__device__ __forceinline__ void cp_wait() {
    asm volatile("cp.async.wait_group %0;" :: "n"(N) : "memory");
}

// ---------------------------------------------------------------------------
// prep_kernel (unchanged, 20.7us):
//   blocks 0..159  : enc/dec projections (tf32 mma, M=32 N=128, K=64 chunks)
//   blocks 160..415: w2 -> g_w2p fp16 fragment pack
// ---------------------------------------------------------------------------
#define PA_STRIDE 272
#define PB_STRIDE 272
#define P_OFF_A   0
#define P_OFF_B   17408
#define P_SMEM    87040

__global__ __launch_bounds__(256) void prep_kernel(
    const float* __restrict__ enc, const float* __restrict__ dec,
    const float* __restrict__ w1, const float* __restrict__ b1,
    const float* __restrict__ w2)
{
    const int bid = blockIdx.x;
    const int tid = threadIdx.x;

    if (bid >= 160) {   // ---- w2 fp16 fragment pack ----
        int t  = (bid - 160) * 256 + tid;
        int l  = t & 31;
        int p  = (t >> 5) & 31;
        int ch = (t >> 10) & 15;
        int nt = t >> 14;
        int n  = nt * 256 + p * 8 + (l >> 2);
        int c0 = ch * 32 + (l & 3) * 2;
        const float* r = w2 + (size_t)n * H_;
        float2 v0 = *(const float2*)(r + c0);
        float2 v1 = *(const float2*)(r + c0 + 8);
        float2 v2 = *(const float2*)(r + c0 + 16);
        float2 v3 = *(const float2*)(r + c0 + 24);
        uint4 q;
        q.x = packh2(v0.x, v0.y);
        q.y = packh2(v1.x, v1.y);
        q.z = packh2(v2.x, v2.y);
        q.w = packh2(v3.x, v3.y);
        g_w2p[((size_t)(nt * 16 + ch) * 32 + p) * 32 + l] = q;
        return;
    }

    extern __shared__ char psm[];
    const uint32_t sbase = smem_u32(psm);

    const int ng = bid & 3;
    const int my = bid >> 2;
    const bool is_dec = (my >= 32);
    const float* A = is_dec ? dec : enc;
    const float* W = is_dec ? (w1 + D_) : w1;
    float* out     = is_dec ? g_dec : g_enc;
    const int m0   = (is_dec ? (my - 32) : my) * 32;
    const int n0   = ng * 128;

    const int lane = tid & 31;
    const int w    = tid >> 5;
    const int wm   = w >> 2;
    const int wn   = w & 3;
    float acc[4][4] = {};

    {
        if (tid < 128) {
            int j = tid;
            #pragma unroll
            for (int i = 0; i < 4; i++, j += 128) {
                int r = j >> 4, seg = j & 15;
                cp16(sbase + P_OFF_A + r * PA_STRIDE + seg * 16,
                     A + (size_t)(m0 + r) * D_ + seg * 4);
            }
        }
        int j = tid;
        #pragma unroll
        for (int i = 0; i < 8; i++, j += 256) {
            int r = j >> 4, seg = j & 15;
            cp16(sbase + P_OFF_B + r * PB_STRIDE + seg * 16,
                 W + (size_t)(n0 + r) * (2 * D_) + seg * 4);
        }
        cp_commit();
    }

    for (int cc = 0; cc < 8; cc++) {
        const int s = cc & 1;
        if (cc < 7) {
            const int sn = s ^ 1;
            const int k0 = (cc + 1) * 64;
            if (tid < 128) {
                int j = tid;
                #pragma unroll
                for (int i = 0; i < 4; i++, j += 128) {
                    int r = j >> 4, seg = j & 15;
                    cp16(sbase + P_OFF_A + sn * 8704 + r * PA_STRIDE + seg * 16,
                         A + (size_t)(m0 + r) * D_ + k0 + seg * 4);
                }
            }
            int j = tid;
            #pragma unroll
            for (int i = 0; i < 8; i++, j += 256) {
                int r = j >> 4, seg = j & 15;
                cp16(sbase + P_OFF_B + sn * 34816 + r * PB_STRIDE + seg * 16,
                     W + (size_t)(n0 + r) * (2 * D_) + k0 + seg * 4);
            }
            cp_commit();
            cp_wait<1>();
        } else {
            cp_wait<0>();
        }
        __syncthreads();

        const float* Af = (const float*)(psm + P_OFF_A + s * 8704);
        const float* Bf = (const float*)(psm + P_OFF_B + s * 34816);

        #pragma unroll
        for (int kk = 0; kk < 8; kk++) {
            int ar = wm * 16 + (lane >> 2);
            int ac = kk * 8 + (lane & 3);
            uint32_t a0 = f2tf32(Af[ar * 68 + ac]);
            uint32_t a1 = f2tf32(Af[(ar + 8) * 68 + ac]);
            uint32_t a2 = f2tf32(Af[ar * 68 + ac + 4]);
            uint32_t a3 = f2tf32(Af[(ar + 8) * 68 + ac + 4]);
            #pragma unroll
            for (int nf = 0; nf < 4; nf++) {
                int br = wn * 32 + nf * 8 + (lane >> 2);
                uint32_t b0 = f2tf32(Bf[br * 68 + ac]);
                uint32_t b1 = f2tf32(Bf[br * 68 + ac + 4]);
                mma_tf32(acc[nf], a0, a1, a2, a3, b0, b1);
            }
        }
        __syncthreads();
    }

    int row = m0 + wm * 16 + (lane >> 2);
    #pragma unroll
    for (int nf = 0; nf < 4; nf++) {
        int cg = n0 + wn * 32 + nf * 8 + (lane & 3) * 2;
        float bv0 = is_dec ? b1[cg]     : 0.0f;
        float bv1 = is_dec ? b1[cg + 1] : 0.0f;
        out[(size_t)row * H_ + cg]           = acc[nf][0] + bv0;
        out[(size_t)row * H_ + cg + 1]       = acc[nf][1] + bv1;
        out[(size_t)(row + 8) * H_ + cg]     = acc[nf][2] + bv0;
        out[(size_t)(row + 8) * H_ + cg + 1] = acc[nf][3] + bv1;
    }
}

// ---------------------------------------------------------------------------
// gemm_fused: one CTA per 128-row m-tile (grid 512), 512 threads (16 warps,
// 4x4 layout, warp tile 32x32). f16-ACCUMULATE MMAs with fp32 promotion
// every K=128 segment.
//  Phase 1: A = gelu(enc+dec) fp16 frag-packed into 128KB SMEM (once).
//  Phase 2: 128 B chunks (8KB, 128 cols x k32), processed in pairs through a
//           3-stage-pair cp.async pipeline; one barrier per pair.
// SMEM: A [0,131072), B pairs at 131072 + sp*16384, sp=0..2 => 180224 B.
// ---------------------------------------------------------------------------
#define FA_BYTES  131072
#define FBP_BYTES 16384                       // one stage-pair (2 x 8KB chunks)
#define SMEM_F    (FA_BYTES + 3 * FBP_BYTES)  // 180224

__global__ __launch_bounds__(512, 1) void gemm_fused(float* __restrict__ out)
{
    extern __shared__ char smem[];
    const uint32_t sbase = smem_u32(smem);
    const int tid  = threadIdx.x;
    const int lane = tid & 31;
    const int w    = tid >> 5;
    const int wm   = w >> 2;          // 0..3 (32 rows each)
    const int wn   = w & 3;           // 0..3 (32 cols each)
    const int mt   = blockIdx.x;      // 0..511

    const uint4* gB = g_w2p;
    // chunk j (j = nt8*16 + ch, nt8 0..7 of 128 cols): source offset in uint4
    //   ((j>>5)*16 + (j&15))*1024 + ((j>>4)&1)*512, length 512 uint4 (8KB)

    // ---- prologue: prefetch pairs 0,1 (chunks 0..3), one commit per pair ----
    #pragma unroll
    for (int pp = 0; pp < 2; pp++) {
        #pragma unroll
        for (int cc = 0; cc < 2; cc++) {
            const int j = 2 * pp + cc;
            const uint4* src = gB + ((j >> 5) * 16 + (j & 15)) * 1024 +
                               ((j >> 4) & 1) * 512 + tid;
            cp16(sbase + FA_BYTES + (pp * 2 + cc) * 8192 + tid * 16, src);
        }
        cp_commit();
    }

    // ---- Phase 1: A generation (fragment order, fp16), 512 threads ----
    {
        const int l   = tid & 31;
        const int mb  = (tid >> 5) & 7;          // row group 0..7 (16 rows)
        const int chb = (tid >> 8) * 8;          // ch split: 0..7 / 8..15
        const int rl  = mb * 16 + (l >> 2);
        const int grow = mt * 128 + rl;
        const int bt   = grow >> 6;
        const int u    = grow & 63;
        const int bat  = grow >> 14;
        const float* ep  = g_enc + (size_t)bt * H_;
        const float* dp0 = g_dec + (size_t)(bat * 64 + u) * H_;
        const float* dp1 = dp0 + 8 * H_;
        uint4* sA = (uint4*)smem;

        #pragma unroll 2
        for (int cho = 0; cho < 8; cho++) {
            const int ch = chb + cho;
            #pragma unroll
            for (int ks = 0; ks < 2; ks++) {
                int cb = ch * 32 + ks * 16 + (l & 3) * 2;
                float2 e0 = *(const float2*)(ep + cb);
                float2 e1 = *(const float2*)(ep + cb + 8);
                float2 a0 = *(const float2*)(dp0 + cb);
                float2 a1 = *(const float2*)(dp0 + cb + 8);
                float2 c0 = *(const float2*)(dp1 + cb);
                float2 c1 = *(const float2*)(dp1 + cb + 8);
                uint4 q;
                q.x = packh2(gelu_tanh(e0.x + a0.x), gelu_tanh(e0.y + a0.y));
                q.y = packh2(gelu_tanh(e0.x + c0.x), gelu_tanh(e0.y + c0.y));
                q.z = packh2(gelu_tanh(e1.x + a1.x), gelu_tanh(e1.y + a1.y));
                q.w = packh2(gelu_tanh(e1.x + c1.x), gelu_tanh(e1.y + c1.y));
                sA[(ch * 16 + mb * 2 + ks) * 32 + l] = q;
            }
        }
    }

    // ---- Phase 2: 64 chunk-pairs; f16-acc MMA, promote every 2 pairs ----
    const size_t rbase = (size_t)mt * 128;
    float    acc[2][4][4] = {};     // fp32 master
    uint32_t hacc[2][4][2] = {};    // f16x2 segment accumulators (+0 packed)

    for (int jp = 0; jp < 64; jp++) {
        cp_wait<1>();        // pair jp landed (pair jp+1 in flight)
        __syncthreads();     // also covers A availability on jp==0

        if (jp + 2 < 64) {   // prefetch pair jp+2 into freed stage-pair
            const int sp2 = (jp + 2) % 3;
            #pragma unroll
            for (int cc = 0; cc < 2; cc++) {
                const int j = 2 * (jp + 2) + cc;
                const uint4* src = gB + ((j >> 5) * 16 + (j & 15)) * 1024 +
                                   ((j >> 4) & 1) * 512 + tid;
                cp16(sbase + FA_BYTES + (sp2 * 2 + cc) * 8192 + tid * 16, src);
            }
        }
        cp_commit();

        const int sp = jp % 3;
        #pragma unroll
        for (int cc = 0; cc < 2; cc++) {
            const int j  = 2 * jp + cc;
            const int ch = j & 15;
            const uint4* sA = (const uint4*)smem + ch * 512;
            const uint4* sB = (const uint4*)(smem + FA_BYTES + (sp * 2 + cc) * 8192);

            uint4 bf[4];
            #pragma unroll
            for (int p = 0; p < 4; p++)
                bf[p] = sB[(wn * 4 + p) * 32 + lane];

            #pragma unroll
            for (int ks = 0; ks < 2; ks++) {
                uint4 af[2];
                #pragma unroll
                for (int mb = 0; mb < 2; mb++)
                    af[mb] = sA[((wm * 2 + mb) * 2 + ks) * 32 + lane];
                #pragma unroll
                for (int mb = 0; mb < 2; mb++) {
                    #pragma unroll
                    for (int p = 0; p < 4; p++) {
                        uint32_t b0 = ks ? bf[p].z : bf[p].x;
                        uint32_t b1 = ks ? bf[p].w : bf[p].y;
                        mma_f16h(hacc[mb][p], af[mb].x, af[mb].y, af[mb].z,
                                 af[mb].w, b0, b1);
                    }
                }
            }
        }

        // promote f16 segment accs -> fp32 master every 2 pairs (K=128)
        if ((jp & 1) == 1) {
            #pragma unroll
            for (int mb = 0; mb < 2; mb++) {
                #pragma unroll
                for (int p = 0; p < 4; p++) {
                    float2 f0 = __half22float2(
                        *reinterpret_cast<__half2*>(&hacc[mb][p][0]));
                    float2 f1 = __half22float2(
                        *reinterpret_cast<__half2*>(&hacc[mb][p][1]));
                    acc[mb][p][0] += f0.x; acc[mb][p][1] += f0.y;
                    acc[mb][p][2] += f1.x; acc[mb][p][3] += f1.y;
                    hacc[mb][p][0] = 0u;   hacc[mb][p][1] = 0u;
                }
            }
        }

        // epilogue after each 8-pair group (one nt8 of 128 columns)
        if ((jp & 7) == 7) {
            const int nt = jp >> 3;
            #pragma unroll
            for (int mb = 0; mb < 2; mb++) {
                size_t r = rbase + wm * 32 + mb * 16 + (lane >> 2);
                #pragma unroll
                for (int p = 0; p < 4; p++) {
                    int cg = nt * 128 + wn * 32 + p * 8 + (lane & 3) * 2;
                    *(float2*)(out + r * V_ + cg) =
                        make_float2(acc[mb][p][0], acc[mb][p][1]);
                    *(float2*)(out + (r + 8) * V_ + cg) =
                        make_float2(acc[mb][p][2], acc[mb][p][3]);
                    acc[mb][p][0] = 0.0f; acc[mb][p][1] = 0.0f;
                    acc[mb][p][2] = 0.0f; acc[mb][p][3] = 0.0f;
                }
            }
        }
    }
}

extern "C" void kernel_launch(void* const* d_in, const int* in_sizes, int n_in,
                              void* d_out, int out_size) {
    const float* enc = (const float*)d_in[0];
    const float* dec = (const float*)d_in[1];
    const float* w1  = (const float*)d_in[2];
    const float* b1  = (const float*)d_in[3];
    const float* w2  = (const float*)d_in[4];
    float* out = (float*)d_out;

    cudaFuncSetAttribute(prep_kernel, cudaFuncAttributeMaxDynamicSharedMemorySize, P_SMEM);
    cudaFuncSetAttribute(gemm_fused, cudaFuncAttributeMaxDynamicSharedMemorySize, SMEM_F);
    prep_kernel<<<416, 256, P_SMEM>>>(enc, dec, w1, b1, w2);
    gemm_fused<<<512, 512, SMEM_F>>>(out);
}

// round 14
// speedup vs baseline: 1.4846x; 1.4846x over previous
#include <cuda_runtime.h>
#include <cuda_fp16.h>
#include <cstdint>

#define B_ 4
#define T_ 256
#define U_ 64
#define D_ 512
#define H_ 512
#define V_ 1024

// ---------------------------------------------------------------------------
// Device-global scratch (allocation-free rule)
// ---------------------------------------------------------------------------
__device__ float g_enc[B_ * T_ * H_];          // 1024 x 512 enc_proj (fp32)
__device__ float g_dec[B_ * U_ * H_];          // 256  x 512 dec_proj + b1 (fp32)
__device__ uint4 g_w2p[4 * 16 * 1024];         // w2 fp16 frag-packed (1 MB)

__device__ __forceinline__ uint32_t f2tf32(float x) {
    uint32_t u; asm("cvt.rna.tf32.f32 %0, %1;" : "=r"(u) : "f"(x)); return u;
}
__device__ __forceinline__ uint32_t packh2(float a, float b) {
    __half2 h = __floats2half2_rn(a, b);
    return *reinterpret_cast<uint32_t*>(&h);
}
__device__ __forceinline__ float gelu_tanh(float x) {
    float t = 0.7978845608028654f * (x + 0.044715f * x * x * x);
    float th; asm("tanh.approx.f32 %0, %1;" : "=f"(th) : "f"(t));
    return 0.5f * x * (1.0f + th);
}
__device__ __forceinline__ uint32_t smem_u32(const void* p) {
    uint32_t a;
    asm("{ .reg .u64 t; cvta.to.shared.u64 t, %1; cvt.u32.u64 %0, t; }" : "=r"(a) : "l"(p));
    return a;
}
__device__ __forceinline__ void mma_tf32(float* acc, uint32_t a0, uint32_t a1,
                                         uint32_t a2, uint32_t a3,
                                         uint32_t b0, uint32_t b1) {
    asm volatile(
        "mma.sync.aligned.m16n8k8.row.col.f32.tf32.tf32.f32 "
        "{%0,%1,%2,%3}, {%4,%5,%6,%7}, {%8,%9}, {%0,%1,%2,%3};"
        : "+f"(acc[0]), "+f"(acc[1]), "+f"(acc[2]), "+f"(acc[3])
        : "r"(a0), "r"(a1), "r"(a2), "r"(a3), "r"(b0), "r"(b1));
}
__device__ __forceinline__ void mma_f16(float* acc, uint32_t a0, uint32_t a1,
                                        uint32_t a2, uint32_t a3,
                                        uint32_t b0, uint32_t b1) {
    asm volatile(
        "mma.sync.aligned.m16n8k16.row.col.f32.f16.f16.f32 "
        "{%0,%1,%2,%3}, {%4,%5,%6,%7}, {%8,%9}, {%0,%1,%2,%3};"
        : "+f"(acc[0]), "+f"(acc[1]), "+f"(acc[2]), "+f"(acc[3])
        : "r"(a0), "r"(a1), "r"(a2), "r"(a3), "r"(b0), "r"(b1));
}
__device__ __forceinline__ void cp16(uint32_t sdst, const void* gsrc) {
    asm volatile("cp.async.cg.shared.global [%0], [%1], 16;" :: "r"(sdst), "l"(gsrc));
}
__device__ __forceinline__ void cp_commit() {
    asm volatile("cp.async.commit_group;" ::: "memory");
}
template <int N>
__device__ __forceinline__ void cp_wait() {
    asm volatile("cp.async.wait_group %0;" :: "n"(N) : "memory");
}

// ---------------------------------------------------------------------------
// prep_kernel (unchanged, 20.7us):
//   blocks 0..159  : enc/dec projections (tf32 mma, M=32 N=128, K=64 chunks)
//   blocks 160..415: w2 -> g_w2p fp16 fragment pack
// ---------------------------------------------------------------------------
#define PA_STRIDE 272
#define PB_STRIDE 272
#define P_OFF_A   0
#define P_OFF_B   17408
#define P_SMEM    87040

__global__ __launch_bounds__(256) void prep_kernel(
    const float* __restrict__ enc, const float* __restrict__ dec,
    const float* __restrict__ w1, const float* __restrict__ b1,
    const float* __restrict__ w2)
{
    const int bid = blockIdx.x;
    const int tid = threadIdx.x;

    if (bid >= 160) {   // ---- w2 fp16 fragment pack ----
        int t  = (bid - 160) * 256 + tid;
        int l  = t & 31;
        int p  = (t >> 5) & 31;
        int ch = (t >> 10) & 15;
        int nt = t >> 14;
        int n  = nt * 256 + p * 8 + (l >> 2);
        int c0 = ch * 32 + (l & 3) * 2;
        const float* r = w2 + (size_t)n * H_;
        float2 v0 = *(const float2*)(r + c0);
        float2 v1 = *(const float2*)(r + c0 + 8);
        float2 v2 = *(const float2*)(r + c0 + 16);
        float2 v3 = *(const float2*)(r + c0 + 24);
        uint4 q;
        q.x = packh2(v0.x, v0.y);
        q.y = packh2(v1.x, v1.y);
        q.z = packh2(v2.x, v2.y);
        q.w = packh2(v3.x, v3.y);
        g_w2p[((size_t)(nt * 16 + ch) * 32 + p) * 32 + l] = q;
        return;
    }

    extern __shared__ char psm[];
    const uint32_t sbase = smem_u32(psm);

    const int ng = bid & 3;
    const int my = bid >> 2;
    const bool is_dec = (my >= 32);
    const float* A = is_dec ? dec : enc;
    const float* W = is_dec ? (w1 + D_) : w1;
    float* out     = is_dec ? g_dec : g_enc;
    const int m0   = (is_dec ? (my - 32) : my) * 32;
    const int n0   = ng * 128;

    const int lane = tid & 31;
    const int w    = tid >> 5;
    const int wm   = w >> 2;
    const int wn   = w & 3;
    float acc[4][4] = {};

    {
        if (tid < 128) {
            int j = tid;
            #pragma unroll
            for (int i = 0; i < 4; i++, j += 128) {
                int r = j >> 4, seg = j & 15;
                cp16(sbase + P_OFF_A + r * PA_STRIDE + seg * 16,
                     A + (size_t)(m0 + r) * D_ + seg * 4);
            }
        }
        int j = tid;
        #pragma unroll
        for (int i = 0; i < 8; i++, j += 256) {
            int r = j >> 4, seg = j & 15;
            cp16(sbase + P_OFF_B + r * PB_STRIDE + seg * 16,
                 W + (size_t)(n0 + r) * (2 * D_) + seg * 4);
        }
        cp_commit();
    }

    for (int cc = 0; cc < 8; cc++) {
        const int s = cc & 1;
        if (cc < 7) {
            const int sn = s ^ 1;
            const int k0 = (cc + 1) * 64;
            if (tid < 128) {
                int j = tid;
                #pragma unroll
                for (int i = 0; i < 4; i++, j += 128) {
                    int r = j >> 4, seg = j & 15;
                    cp16(sbase + P_OFF_A + sn * 8704 + r * PA_STRIDE + seg * 16,
                         A + (size_t)(m0 + r) * D_ + k0 + seg * 4);
                }
            }
            int j = tid;
            #pragma unroll
            for (int i = 0; i < 8; i++, j += 256) {
                int r = j >> 4, seg = j & 15;
                cp16(sbase + P_OFF_B + sn * 34816 + r * PB_STRIDE + seg * 16,
                     W + (size_t)(n0 + r) * (2 * D_) + k0 + seg * 4);
            }
            cp_commit();
            cp_wait<1>();
        } else {
            cp_wait<0>();
        }
        __syncthreads();

        const float* Af = (const float*)(psm + P_OFF_A + s * 8704);
        const float* Bf = (const float*)(psm + P_OFF_B + s * 34816);

        #pragma unroll
        for (int kk = 0; kk < 8; kk++) {
            int ar = wm * 16 + (lane >> 2);
            int ac = kk * 8 + (lane & 3);
            uint32_t a0 = f2tf32(Af[ar * 68 + ac]);
            uint32_t a1 = f2tf32(Af[(ar + 8) * 68 + ac]);
            uint32_t a2 = f2tf32(Af[ar * 68 + ac + 4]);
            uint32_t a3 = f2tf32(Af[(ar + 8) * 68 + ac + 4]);
            #pragma unroll
            for (int nf = 0; nf < 4; nf++) {
                int br = wn * 32 + nf * 8 + (lane >> 2);
                uint32_t b0 = f2tf32(Bf[br * 68 + ac]);
                uint32_t b1 = f2tf32(Bf[br * 68 + ac + 4]);
                mma_tf32(acc[nf], a0, a1, a2, a3, b0, b1);
            }
        }
        __syncthreads();
    }

    int row = m0 + wm * 16 + (lane >> 2);
    #pragma unroll
    for (int nf = 0; nf < 4; nf++) {
        int cg = n0 + wn * 32 + nf * 8 + (lane & 3) * 2;
        float bv0 = is_dec ? b1[cg]     : 0.0f;
        float bv1 = is_dec ? b1[cg + 1] : 0.0f;
        out[(size_t)row * H_ + cg]           = acc[nf][0] + bv0;
        out[(size_t)row * H_ + cg + 1]       = acc[nf][1] + bv1;
        out[(size_t)(row + 8) * H_ + cg]     = acc[nf][2] + bv0;
        out[(size_t)(row + 8) * H_ + cg + 1] = acc[nf][3] + bv1;
    }
}

// ---------------------------------------------------------------------------
// gemm_fused: one CTA per 128-row m-tile (grid 512), 256 threads / 8 warps.
// Warp tile 128x32: each warp owns ALL rows x a private 32-col slice, with
// its OWN 4-stage cp.async B ring (2KB/chunk). ZERO block barriers in the
// main loop (A is read-only SMEM after one __syncthreads; cp.async groups
// are per-warp). f32-accumulate m16n8k16.
// SMEM: A [0,131072), per-warp B rings at 131072 + w*8192 => 196608 B.
// ---------------------------------------------------------------------------
#define FA_BYTES  131072
#define WB_RING   8192                        // 4 stages x 2KB per warp
#define SMEM_F    (FA_BYTES + 8 * WB_RING)    // 196608

__global__ __launch_bounds__(256, 1) void gemm_fused(float* __restrict__ out)
{
    extern __shared__ char smem[];
    const uint32_t sbase = smem_u32(smem);
    const int tid  = threadIdx.x;
    const int lane = tid & 31;
    const int w    = tid >> 5;        // 0..7 = 32-col slice owner
    const int mt   = blockIdx.x;      // 0..511

    const uint4* gB = g_w2p;
    const uint32_t wring = sbase + FA_BYTES + w * WB_RING;

    // ---- prologue: this warp's slices of chunks 0,1,2 into stages 0,1,2 ----
    // chunk j slice: gB[j*1024 + w*128 + q*32 + lane], q=0..3 (2KB total)
    #pragma unroll
    for (int j = 0; j < 3; j++) {
        #pragma unroll
        for (int q = 0; q < 4; q++)
            cp16(wring + j * 2048 + q * 512 + lane * 16,
                 gB + (size_t)j * 1024 + w * 128 + q * 32 + lane);
        cp_commit();
    }

    // ---- Phase 1: A = gelu(enc+dec), fp16 fragment order (as R10) ----
    {
        const int l  = tid & 31;
        const int mb = (tid >> 5) & 7;
        const int rl = mb * 16 + (l >> 2);
        const int grow = mt * 128 + rl;
        const int bt   = grow >> 6;
        const int u    = grow & 63;
        const int bat  = grow >> 14;
        const float* ep  = g_enc + (size_t)bt * H_;
        const float* dp0 = g_dec + (size_t)(bat * 64 + u) * H_;
        const float* dp1 = dp0 + 8 * H_;
        uint4* sA = (uint4*)smem;

        #pragma unroll 2
        for (int ch = 0; ch < 16; ch++) {
            #pragma unroll
            for (int ks = 0; ks < 2; ks++) {
                int cb = ch * 32 + ks * 16 + (l & 3) * 2;
                float2 e0 = *(const float2*)(ep + cb);
                float2 e1 = *(const float2*)(ep + cb + 8);
                float2 a0 = *(const float2*)(dp0 + cb);
                float2 a1 = *(const float2*)(dp0 + cb + 8);
                float2 c0 = *(const float2*)(dp1 + cb);
                float2 c1 = *(const float2*)(dp1 + cb + 8);
                uint4 q;
                q.x = packh2(gelu_tanh(e0.x + a0.x), gelu_tanh(e0.y + a0.y));
                q.y = packh2(gelu_tanh(e0.x + c0.x), gelu_tanh(e0.y + c0.y));
                q.z = packh2(gelu_tanh(e1.x + a1.x), gelu_tanh(e1.y + a1.y));
                q.w = packh2(gelu_tanh(e1.x + c1.x), gelu_tanh(e1.y + c1.y));
                sA[(ch * 16 + mb * 2 + ks) * 32 + l] = q;
            }
        }
    }
    __syncthreads();   // the ONLY block-wide barrier

    // ---- Phase 2: 64 chunks, per-warp ring, barrier-free ----
    const size_t rbase = (size_t)mt * 128;
    float acc[8][4][4] = {};          // mb(8 x m16) x p(4 x n8) x 4

    for (int j = 0; j < 64; j++) {
        cp_wait<2>();                 // this warp's chunk j landed

        // prefetch chunk j+3 into stage (j+3)&3 (this warp used it at j-1)
        if (j + 3 < 64) {
            const int s3 = (j + 3) & 3;
            #pragma unroll
            for (int q = 0; q < 4; q++)
                cp16(wring + s3 * 2048 + q * 512 + lane * 16,
                     gB + (size_t)(j + 3) * 1024 + w * 128 + q * 32 + lane);
        }
        cp_commit();

        const int s  = j & 3;
        const int ch = j & 15;
        const uint4* sBw = (const uint4*)(smem + FA_BYTES + w * WB_RING + s * 2048);
        const uint4* sA  = (const uint4*)smem + ch * 512;

        uint4 bf[4];
        #pragma unroll
        for (int p = 0; p < 4; p++)
            bf[p] = sBw[p * 32 + lane];

        #pragma unroll
        for (int ks = 0; ks < 2; ks++) {
            uint4 af[8];
            #pragma unroll
            for (int mb = 0; mb < 8; mb++)
                af[mb] = sA[(mb * 2 + ks) * 32 + lane];
            #pragma unroll
            for (int mb = 0; mb < 8; mb++) {
                #pragma unroll
                for (int p = 0; p < 4; p++) {
                    uint32_t b0 = ks ? bf[p].z : bf[p].x;
                    uint32_t b1 = ks ? bf[p].w : bf[p].y;
                    mma_f16(acc[mb][p], af[mb].x, af[mb].y, af[mb].z, af[mb].w,
                            b0, b1);
                }
            }
        }

        // epilogue per nt group (16 chunks = 256 cols; warp owns 32 of them)
        if ((j & 15) == 15) {
            const int nt = j >> 4;
            #pragma unroll
            for (int mb = 0; mb < 8; mb++) {
                size_t r = rbase + mb * 16 + (lane >> 2);
                #pragma unroll
                for (int p = 0; p < 4; p++) {
                    int cg = nt * 256 + w * 32 + p * 8 + (lane & 3) * 2;
                    *(float2*)(out + r * V_ + cg) =
                        make_float2(acc[mb][p][0], acc[mb][p][1]);
                    *(float2*)(out + (r + 8) * V_ + cg) =
                        make_float2(acc[mb][p][2], acc[mb][p][3]);
                    acc[mb][p][0] = 0.0f; acc[mb][p][1] = 0.0f;
                    acc[mb][p][2] = 0.0f; acc[mb][p][3] = 0.0f;
                }
            }
        }
    }
}

extern "C" void kernel_launch(void* const* d_in, const int* in_sizes, int n_in,
                              void* d_out, int out_size) {
    const float* enc = (const float*)d_in[0];
    const float* dec = (const float*)d_in[1];
    const float* w1  = (const float*)d_in[2];
    const float* b1  = (const float*)d_in[3];
    const float* w2  = (const float*)d_in[4];
    float* out = (float*)d_out;

    cudaFuncSetAttribute(prep_kernel, cudaFuncAttributeMaxDynamicSharedMemorySize, P_SMEM);
    cudaFuncSetAttribute(gemm_fused, cudaFuncAttributeMaxDynamicSharedMemorySize, SMEM_F);
    prep_kernel<<<416, 256, P_SMEM>>>(enc, dec, w1, b1, w2);
    gemm_fused<<<512, 256, SMEM_F>>>(out);
}

// round 15
// speedup vs baseline: 2.0641x; 1.3903x over previous
#include <cuda_runtime.h>
#include <cuda_fp16.h>
#include <cstdint>

#define B_ 4
#define T_ 256
#define U_ 64
#define D_ 512
#define H_ 512
#define V_ 1024

// ---------------------------------------------------------------------------
// Device-global scratch (allocation-free rule)
// ---------------------------------------------------------------------------
__device__ float g_enc[B_ * T_ * H_];          // 1024 x 512 enc_proj (fp32)
__device__ float g_dec[B_ * U_ * H_];          // 256  x 512 dec_proj + b1 (fp32)
__device__ uint4 g_w2p[4 * 16 * 1024];         // w2 fp16 frag-packed (1 MB)

__device__ __forceinline__ uint32_t f2tf32(float x) {
    uint32_t u; asm("cvt.rna.tf32.f32 %0, %1;" : "=r"(u) : "f"(x)); return u;
}
__device__ __forceinline__ uint32_t packh2(float a, float b) {
    __half2 h = __floats2half2_rn(a, b);
    return *reinterpret_cast<uint32_t*>(&h);
}
__device__ __forceinline__ float gelu_tanh(float x) {
    float t = 0.7978845608028654f * (x + 0.044715f * x * x * x);
    float th; asm("tanh.approx.f32 %0, %1;" : "=f"(th) : "f"(t));
    return 0.5f * x * (1.0f + th);
}
__device__ __forceinline__ uint32_t smem_u32(const void* p) {
    uint32_t a;
    asm("{ .reg .u64 t; cvta.to.shared.u64 t, %1; cvt.u32.u64 %0, t; }" : "=r"(a) : "l"(p));
    return a;
}
__device__ __forceinline__ void mma_tf32(float* acc, uint32_t a0, uint32_t a1,
                                         uint32_t a2, uint32_t a3,
                                         uint32_t b0, uint32_t b1) {
    asm volatile(
        "mma.sync.aligned.m16n8k8.row.col.f32.tf32.tf32.f32 "
        "{%0,%1,%2,%3}, {%4,%5,%6,%7}, {%8,%9}, {%0,%1,%2,%3};"
        : "+f"(acc[0]), "+f"(acc[1]), "+f"(acc[2]), "+f"(acc[3])
        : "r"(a0), "r"(a1), "r"(a2), "r"(a3), "r"(b0), "r"(b1));
}
__device__ __forceinline__ void mma_f16(float* acc, uint32_t a0, uint32_t a1,
                                        uint32_t a2, uint32_t a3,
                                        uint32_t b0, uint32_t b1) {
    asm volatile(
        "mma.sync.aligned.m16n8k16.row.col.f32.f16.f16.f32 "
        "{%0,%1,%2,%3}, {%4,%5,%6,%7}, {%8,%9}, {%0,%1,%2,%3};"
        : "+f"(acc[0]), "+f"(acc[1]), "+f"(acc[2]), "+f"(acc[3])
        : "r"(a0), "r"(a1), "r"(a2), "r"(a3), "r"(b0), "r"(b1));
}
__device__ __forceinline__ void cp16(uint32_t sdst, const void* gsrc) {
    asm volatile("cp.async.cg.shared.global [%0], [%1], 16;" :: "r"(sdst), "l"(gsrc));
}
__device__ __forceinline__ void cp_commit() {
    asm volatile("cp.async.commit_group;" ::: "memory");
}
template <int N>
__device__ __forceinline__ void cp_wait() {
    asm volatile("cp.async.wait_group %0;" :: "n"(N) : "memory");
}

// ---------------------------------------------------------------------------
// prep_kernel (unchanged, 20.7us):
//   blocks 0..159  : enc/dec projections (tf32 mma, M=32 N=128, K=64 chunks)
//   blocks 160..415: w2 -> g_w2p fp16 fragment pack
// ---------------------------------------------------------------------------
#define PA_STRIDE 272
#define PB_STRIDE 272
#define P_OFF_A   0
#define P_OFF_B   17408
#define P_SMEM    87040

__global__ __launch_bounds__(256) void prep_kernel(
    const float* __restrict__ enc, const float* __restrict__ dec,
    const float* __restrict__ w1, const float* __restrict__ b1,
    const float* __restrict__ w2)
{
    const int bid = blockIdx.x;
    const int tid = threadIdx.x;

    if (bid >= 160) {   // ---- w2 fp16 fragment pack ----
        int t  = (bid - 160) * 256 + tid;
        int l  = t & 31;
        int p  = (t >> 5) & 31;
        int ch = (t >> 10) & 15;
        int nt = t >> 14;
        int n  = nt * 256 + p * 8 + (l >> 2);
        int c0 = ch * 32 + (l & 3) * 2;
        const float* r = w2 + (size_t)n * H_;
        float2 v0 = *(const float2*)(r + c0);
        float2 v1 = *(const float2*)(r + c0 + 8);
        float2 v2 = *(const float2*)(r + c0 + 16);
        float2 v3 = *(const float2*)(r + c0 + 24);
        uint4 q;
        q.x = packh2(v0.x, v0.y);
        q.y = packh2(v1.x, v1.y);
        q.z = packh2(v2.x, v2.y);
        q.w = packh2(v3.x, v3.y);
        g_w2p[((size_t)(nt * 16 + ch) * 32 + p) * 32 + l] = q;
        return;
    }

    extern __shared__ char psm[];
    const uint32_t sbase = smem_u32(psm);

    const int ng = bid & 3;
    const int my = bid >> 2;
    const bool is_dec = (my >= 32);
    const float* A = is_dec ? dec : enc;
    const float* W = is_dec ? (w1 + D_) : w1;
    float* out     = is_dec ? g_dec : g_enc;
    const int m0   = (is_dec ? (my - 32) : my) * 32;
    const int n0   = ng * 128;

    const int lane = tid & 31;
    const int w    = tid >> 5;
    const int wm   = w >> 2;
    const int wn   = w & 3;
    float acc[4][4] = {};

    {
        if (tid < 128) {
            int j = tid;
            #pragma unroll
            for (int i = 0; i < 4; i++, j += 128) {
                int r = j >> 4, seg = j & 15;
                cp16(sbase + P_OFF_A + r * PA_STRIDE + seg * 16,
                     A + (size_t)(m0 + r) * D_ + seg * 4);
            }
        }
        int j = tid;
        #pragma unroll
        for (int i = 0; i < 8; i++, j += 256) {
            int r = j >> 4, seg = j & 15;
            cp16(sbase + P_OFF_B + r * PB_STRIDE + seg * 16,
                 W + (size_t)(n0 + r) * (2 * D_) + seg * 4);
        }
        cp_commit();
    }

    for (int cc = 0; cc < 8; cc++) {
        const int s = cc & 1;
        if (cc < 7) {
            const int sn = s ^ 1;
            const int k0 = (cc + 1) * 64;
            if (tid < 128) {
                int j = tid;
                #pragma unroll
                for (int i = 0; i < 4; i++, j += 128) {
                    int r = j >> 4, seg = j & 15;
                    cp16(sbase + P_OFF_A + sn * 8704 + r * PA_STRIDE + seg * 16,
                         A + (size_t)(m0 + r) * D_ + k0 + seg * 4);
                }
            }
            int j = tid;
            #pragma unroll
            for (int i = 0; i < 8; i++, j += 256) {
                int r = j >> 4, seg = j & 15;
                cp16(sbase + P_OFF_B + sn * 34816 + r * PB_STRIDE + seg * 16,
                     W + (size_t)(n0 + r) * (2 * D_) + k0 + seg * 4);
            }
            cp_commit();
            cp_wait<1>();
        } else {
            cp_wait<0>();
        }
        __syncthreads();

        const float* Af = (const float*)(psm + P_OFF_A + s * 8704);
        const float* Bf = (const float*)(psm + P_OFF_B + s * 34816);

        #pragma unroll
        for (int kk = 0; kk < 8; kk++) {
            int ar = wm * 16 + (lane >> 2);
            int ac = kk * 8 + (lane & 3);
            uint32_t a0 = f2tf32(Af[ar * 68 + ac]);
            uint32_t a1 = f2tf32(Af[(ar + 8) * 68 + ac]);
            uint32_t a2 = f2tf32(Af[ar * 68 + ac + 4]);
            uint32_t a3 = f2tf32(Af[(ar + 8) * 68 + ac + 4]);
            #pragma unroll
            for (int nf = 0; nf < 4; nf++) {
                int br = wn * 32 + nf * 8 + (lane >> 2);
                uint32_t b0 = f2tf32(Bf[br * 68 + ac]);
                uint32_t b1 = f2tf32(Bf[br * 68 + ac + 4]);
                mma_tf32(acc[nf], a0, a1, a2, a3, b0, b1);
            }
        }
        __syncthreads();
    }

    int row = m0 + wm * 16 + (lane >> 2);
    #pragma unroll
    for (int nf = 0; nf < 4; nf++) {
        int cg = n0 + wn * 32 + nf * 8 + (lane & 3) * 2;
        float bv0 = is_dec ? b1[cg]     : 0.0f;
        float bv1 = is_dec ? b1[cg + 1] : 0.0f;
        out[(size_t)row * H_ + cg]           = acc[nf][0] + bv0;
        out[(size_t)row * H_ + cg + 1]       = acc[nf][1] + bv1;
        out[(size_t)(row + 8) * H_ + cg]     = acc[nf][2] + bv0;
        out[(size_t)(row + 8) * H_ + cg + 1] = acc[nf][3] + bv1;
    }
}

// ---------------------------------------------------------------------------
// gemm_fused: M=64 tiles (one bt each), grid 1024, 256 threads, 2 CTAs/SM.
// Warp layout 2(m:32) x 4(n:32); acc = 32 regs. f32-acc m16n8k16.
//  Phase 1: A = gelu(enc+dec) fp16 frag-packed into 64KB SMEM (once).
//  Phase 2: 128 B chunks (8KB = 128 cols x k32), processed in PAIRS through
//           a 3-stage-pair cp.async pipeline; one barrier per pair.
// SMEM: A [0,65536), B pairs at 65536 + sp*16384, sp=0..2 => 114688 B.
// chunk j (j = nt8*16 + ch): src uint4 = ((j>>5)*16 + (j&15))*1024
//                                        + ((j>>4)&1)*512, len 512.
// ---------------------------------------------------------------------------
#define FA_BYTES  65536
#define FBP_BYTES 16384                       // one stage-pair (2 x 8KB)
#define SMEM_F    (FA_BYTES + 3 * FBP_BYTES)  // 114688

__global__ __launch_bounds__(256, 2) void gemm_fused(float* __restrict__ out)
{
    extern __shared__ char smem[];
    const uint32_t sbase = smem_u32(smem);
    const int tid  = threadIdx.x;
    const int lane = tid & 31;
    const int w    = tid >> 5;
    const int wm   = w >> 2;          // 0..1 (32 rows each)
    const int wn   = w & 3;           // 0..3 (32 cols each)
    const int mt   = blockIdx.x;      // 0..1023 (= bt)

    const uint4* gB = g_w2p;

    // ---- prologue: prefetch pairs 0,1 (chunks 0..3), one commit per pair ----
    #pragma unroll
    for (int pp = 0; pp < 2; pp++) {
        #pragma unroll
        for (int cc = 0; cc < 2; cc++) {
            const int j = 2 * pp + cc;
            const uint4* src = gB + ((j >> 5) * 16 + (j & 15)) * 1024 +
                               ((j >> 4) & 1) * 512 + tid;
            uint32_t dst = sbase + FA_BYTES + (pp * 2 + cc) * 8192 + tid * 16;
            cp16(dst, src);
            cp16(dst + 4096, src + 256);
        }
        cp_commit();
    }

    // ---- Phase 1: A = gelu(enc+dec), fp16 fragment order, 64 rows ----
    {
        const int l    = tid & 31;
        const int mb2  = (tid >> 5) & 3;         // 16-row group 0..3
        const int half = tid >> 7;               // ch split 0..7 / 8..15
        const int rl   = mb2 * 16 + (l >> 2);    // row in tile = u
        const int bat  = mt >> 8;
        const float* ep  = g_enc + (size_t)mt * H_;
        const float* dp0 = g_dec + (size_t)(bat * 64 + rl) * H_;
        const float* dp1 = dp0 + 8 * H_;
        uint4* sA = (uint4*)smem;

        #pragma unroll 2
        for (int cho = 0; cho < 8; cho++) {
            const int ch = half * 8 + cho;
            #pragma unroll
            for (int ks = 0; ks < 2; ks++) {
                int cb = ch * 32 + ks * 16 + (l & 3) * 2;
                float2 e0 = *(const float2*)(ep + cb);
                float2 e1 = *(const float2*)(ep + cb + 8);
                float2 a0 = *(const float2*)(dp0 + cb);
                float2 a1 = *(const float2*)(dp0 + cb + 8);
                float2 c0 = *(const float2*)(dp1 + cb);
                float2 c1 = *(const float2*)(dp1 + cb + 8);
                uint4 q;
                q.x = packh2(gelu_tanh(e0.x + a0.x), gelu_tanh(e0.y + a0.y));
                q.y = packh2(gelu_tanh(e0.x + c0.x), gelu_tanh(e0.y + c0.y));
                q.z = packh2(gelu_tanh(e1.x + a1.x), gelu_tanh(e1.y + a1.y));
                q.w = packh2(gelu_tanh(e1.x + c1.x), gelu_tanh(e1.y + c1.y));
                sA[(ch * 8 + mb2 * 2 + ks) * 32 + l] = q;
            }
        }
    }

    // ---- Phase 2: 64 chunk-pairs, one barrier per pair ----
    const size_t rbase = (size_t)mt * 64;
    float acc[2][4][4] = {};

    for (int jp = 0; jp < 64; jp++) {
        cp_wait<1>();        // pair jp landed (pair jp+1 in flight)
        __syncthreads();     // also covers A availability on jp==0

        if (jp + 2 < 64) {   // prefetch pair jp+2 into freed stage-pair
            const int sp2 = (jp + 2) % 3;
            #pragma unroll
            for (int cc = 0; cc < 2; cc++) {
                const int j = 2 * (jp + 2) + cc;
                const uint4* src = gB + ((j >> 5) * 16 + (j & 15)) * 1024 +
                                   ((j >> 4) & 1) * 512 + tid;
                uint32_t dst = sbase + FA_BYTES + (sp2 * 2 + cc) * 8192 + tid * 16;
                cp16(dst, src);
                cp16(dst + 4096, src + 256);
            }
        }
        cp_commit();

        const int sp = jp % 3;
        #pragma unroll
        for (int cc = 0; cc < 2; cc++) {
            const int j  = 2 * jp + cc;
            const int ch = j & 15;
            const uint4* sA = (const uint4*)smem + ch * 256;
            const uint4* sB = (const uint4*)(smem + FA_BYTES + (sp * 2 + cc) * 8192);

            uint4 bf[4];
            #pragma unroll
            for (int p = 0; p < 4; p++)
                bf[p] = sB[(wn * 4 + p) * 32 + lane];

            #pragma unroll
            for (int ks = 0; ks < 2; ks++) {
                uint4 af[2];
                #pragma unroll
                for (int mb = 0; mb < 2; mb++)
                    af[mb] = sA[((wm * 2 + mb) * 2 + ks) * 32 + lane];
                #pragma unroll
                for (int mb = 0; mb < 2; mb++) {
                    #pragma unroll
                    for (int p = 0; p < 4; p++) {
                        uint32_t b0 = ks ? bf[p].z : bf[p].x;
                        uint32_t b1 = ks ? bf[p].w : bf[p].y;
                        mma_f16(acc[mb][p], af[mb].x, af[mb].y, af[mb].z,
                                af[mb].w, b0, b1);
                    }
                }
            }
        }

        // epilogue after each 8-pair group (one nt8 of 128 columns)
        if ((jp & 7) == 7) {
            const int nt8 = jp >> 3;
            #pragma unroll
            for (int mb = 0; mb < 2; mb++) {
                size_t r = rbase + wm * 32 + mb * 16 + (lane >> 2);
                #pragma unroll
                for (int p = 0; p < 4; p++) {
                    int cg = nt8 * 128 + wn * 32 + p * 8 + (lane & 3) * 2;
                    *(float2*)(out + r * V_ + cg) =
                        make_float2(acc[mb][p][0], acc[mb][p][1]);
                    *(float2*)(out + (r + 8) * V_ + cg) =
                        make_float2(acc[mb][p][2], acc[mb][p][3]);
                    acc[mb][p][0] = 0.0f; acc[mb][p][1] = 0.0f;
                    acc[mb][p][2] = 0.0f; acc[mb][p][3] = 0.0f;
                }
            }
        }
    }
}

extern "C" void kernel_launch(void* const* d_in, const int* in_sizes, int n_in,
                              void* d_out, int out_size) {
    const float* enc = (const float*)d_in[0];
    const float* dec = (const float*)d_in[1];
    const float* w1  = (const float*)d_in[2];
    const float* b1  = (const float*)d_in[3];
    const float* w2  = (const float*)d_in[4];
    float* out = (float*)d_out;

    cudaFuncSetAttribute(prep_kernel, cudaFuncAttributeMaxDynamicSharedMemorySize, P_SMEM);
    cudaFuncSetAttribute(gemm_fused, cudaFuncAttributeMaxDynamicSharedMemorySize, SMEM_F);
    prep_kernel<<<416, 256, P_SMEM>>>(enc, dec, w1, b1, w2);
    gemm_fused<<<1024, 256, SMEM_F>>>(out);
}

// round 16
// speedup vs baseline: 2.1368x; 1.0352x over previous
#include <cuda_runtime.h>
#include <cuda_fp16.h>
#include <cstdint>

#define B_ 4
#define T_ 256
#define U_ 64
#define D_ 512
#define H_ 512
#define V_ 1024

// ---------------------------------------------------------------------------
// Device-global scratch (allocation-free rule)
// ---------------------------------------------------------------------------
__device__ float g_enc[B_ * T_ * H_];          // 1024 x 512 enc_proj (fp32)
__device__ float g_dec[B_ * U_ * H_];          // 256  x 512 dec_proj + b1 (fp32)
__device__ uint4 g_w2p[128 * 512];             // w2 fp16, CHUNK-LINEAR packed (1 MB)

__device__ __forceinline__ uint32_t f2tf32(float x) {
    uint32_t u; asm("cvt.rna.tf32.f32 %0, %1;" : "=r"(u) : "f"(x)); return u;
}
__device__ __forceinline__ uint32_t packh2(float a, float b) {
    __half2 h = __floats2half2_rn(a, b);
    return *reinterpret_cast<uint32_t*>(&h);
}
__device__ __forceinline__ float gelu_tanh(float x) {
    float t = 0.7978845608028654f * (x + 0.044715f * x * x * x);
    float th; asm("tanh.approx.f32 %0, %1;" : "=f"(th) : "f"(t));
    return 0.5f * x * (1.0f + th);
}
__device__ __forceinline__ uint32_t smem_u32(const void* p) {
    uint32_t a;
    asm("{ .reg .u64 t; cvta.to.shared.u64 t, %1; cvt.u32.u64 %0, t; }" : "=r"(a) : "l"(p));
    return a;
}
__device__ __forceinline__ void mma_tf32(float* acc, uint32_t a0, uint32_t a1,
                                         uint32_t a2, uint32_t a3,
                                         uint32_t b0, uint32_t b1) {
    asm volatile(
        "mma.sync.aligned.m16n8k8.row.col.f32.tf32.tf32.f32 "
        "{%0,%1,%2,%3}, {%4,%5,%6,%7}, {%8,%9}, {%0,%1,%2,%3};"
        : "+f"(acc[0]), "+f"(acc[1]), "+f"(acc[2]), "+f"(acc[3])
        : "r"(a0), "r"(a1), "r"(a2), "r"(a3), "r"(b0), "r"(b1));
}
__device__ __forceinline__ void mma_f16(float* acc, uint32_t a0, uint32_t a1,
                                        uint32_t a2, uint32_t a3,
                                        uint32_t b0, uint32_t b1) {
    asm volatile(
        "mma.sync.aligned.m16n8k16.row.col.f32.f16.f16.f32 "
        "{%0,%1,%2,%3}, {%4,%5,%6,%7}, {%8,%9}, {%0,%1,%2,%3};"
        : "+f"(acc[0]), "+f"(acc[1]), "+f"(acc[2]), "+f"(acc[3])
        : "r"(a0), "r"(a1), "r"(a2), "r"(a3), "r"(b0), "r"(b1));
}
__device__ __forceinline__ void cp16(uint32_t sdst, const void* gsrc) {
    asm volatile("cp.async.cg.shared.global [%0], [%1], 16;" :: "r"(sdst), "l"(gsrc));
}
__device__ __forceinline__ void cp_commit() {
    asm volatile("cp.async.commit_group;" ::: "memory");
}
template <int N>
__device__ __forceinline__ void cp_wait() {
    asm volatile("cp.async.wait_group %0;" :: "n"(N) : "memory");
}

// ---------------------------------------------------------------------------
// prep_kernel:
//   blocks 0..159  : enc/dec projections (tf32 mma, M=32 N=128, K=64 chunks)
//   blocks 160..415: w2 -> g_w2p fp16 pack, CHUNK-LINEAR:
//     chunk j (= nt8*16 + ch; nt8 = 128-col group, ch = k32 group) occupies
//     g_w2p[j*512 .. j*512+512). Within: slot (p8, l), p8=0..15, l=0..31:
//       n  = nt8*128 + p8*8 + (l>>2)   (output column / w2 row)
//       c0 = ch*32 + (l&3)*2           (k position)
//       uint4 = {h2(n,c0), h2(n,c0+8), h2(n,c0+16), h2(n,c0+24)}
// ---------------------------------------------------------------------------
#define PA_STRIDE 272
#define PB_STRIDE 272
#define P_OFF_A   0
#define P_OFF_B   17408
#define P_SMEM    87040

__global__ __launch_bounds__(256) void prep_kernel(
    const float* __restrict__ enc, const float* __restrict__ dec,
    const float* __restrict__ w1, const float* __restrict__ b1,
    const float* __restrict__ w2)
{
    const int bid = blockIdx.x;
    const int tid = threadIdx.x;

    if (bid >= 160) {   // ---- w2 fp16 pack, chunk-linear ----
        int t   = (bid - 160) * 256 + tid;      // 0..65535
        int l   = t & 31;
        int p8  = (t >> 5) & 15;
        int j   = t >> 9;                       // 0..127
        int ch  = j & 15;
        int nt8 = j >> 4;
        int n   = nt8 * 128 + p8 * 8 + (l >> 2);
        int c0  = ch * 32 + (l & 3) * 2;
        const float* r = w2 + (size_t)n * H_;
        float2 v0 = *(const float2*)(r + c0);
        float2 v1 = *(const float2*)(r + c0 + 8);
        float2 v2 = *(const float2*)(r + c0 + 16);
        float2 v3 = *(const float2*)(r + c0 + 24);
        uint4 q;
        q.x = packh2(v0.x, v0.y);
        q.y = packh2(v1.x, v1.y);
        q.z = packh2(v2.x, v2.y);
        q.w = packh2(v3.x, v3.y);
        g_w2p[((size_t)j * 16 + p8) * 32 + l] = q;
        return;
    }

    extern __shared__ char psm[];
    const uint32_t sbase = smem_u32(psm);

    const int ng = bid & 3;
    const int my = bid >> 2;
    const bool is_dec = (my >= 32);
    const float* A = is_dec ? dec : enc;
    const float* W = is_dec ? (w1 + D_) : w1;
    float* out     = is_dec ? g_dec : g_enc;
    const int m0   = (is_dec ? (my - 32) : my) * 32;
    const int n0   = ng * 128;

    const int lane = tid & 31;
    const int w    = tid >> 5;
    const int wm   = w >> 2;
    const int wn   = w & 3;
    float acc[4][4] = {};

    {
        if (tid < 128) {
            int j = tid;
            #pragma unroll
            for (int i = 0; i < 4; i++, j += 128) {
                int r = j >> 4, seg = j & 15;
                cp16(sbase + P_OFF_A + r * PA_STRIDE + seg * 16,
                     A + (size_t)(m0 + r) * D_ + seg * 4);
            }
        }
        int j = tid;
        #pragma unroll
        for (int i = 0; i < 8; i++, j += 256) {
            int r = j >> 4, seg = j & 15;
            cp16(sbase + P_OFF_B + r * PB_STRIDE + seg * 16,
                 W + (size_t)(n0 + r) * (2 * D_) + seg * 4);
        }
        cp_commit();
    }

    for (int cc = 0; cc < 8; cc++) {
        const int s = cc & 1;
        if (cc < 7) {
            const int sn = s ^ 1;
            const int k0 = (cc + 1) * 64;
            if (tid < 128) {
                int j = tid;
                #pragma unroll
                for (int i = 0; i < 4; i++, j += 128) {
                    int r = j >> 4, seg = j & 15;
                    cp16(sbase + P_OFF_A + sn * 8704 + r * PA_STRIDE + seg * 16,
                         A + (size_t)(m0 + r) * D_ + k0 + seg * 4);
                }
            }
            int j = tid;
            #pragma unroll
            for (int i = 0; i < 8; i++, j += 256) {
                int r = j >> 4, seg = j & 15;
                cp16(sbase + P_OFF_B + sn * 34816 + r * PB_STRIDE + seg * 16,
                     W + (size_t)(n0 + r) * (2 * D_) + k0 + seg * 4);
            }
            cp_commit();
            cp_wait<1>();
        } else {
            cp_wait<0>();
        }
        __syncthreads();

        const float* Af = (const float*)(psm + P_OFF_A + s * 8704);
        const float* Bf = (const float*)(psm + P_OFF_B + s * 34816);

        #pragma unroll
        for (int kk = 0; kk < 8; kk++) {
            int ar = wm * 16 + (lane >> 2);
            int ac = kk * 8 + (lane & 3);
            uint32_t a0 = f2tf32(Af[ar * 68 + ac]);
            uint32_t a1 = f2tf32(Af[(ar + 8) * 68 + ac]);
            uint32_t a2 = f2tf32(Af[ar * 68 + ac + 4]);
            uint32_t a3 = f2tf32(Af[(ar + 8) * 68 + ac + 4]);
            #pragma unroll
            for (int nf = 0; nf < 4; nf++) {
                int br = wn * 32 + nf * 8 + (lane >> 2);
                uint32_t b0 = f2tf32(Bf[br * 68 + ac]);
                uint32_t b1 = f2tf32(Bf[br * 68 + ac + 4]);
                mma_tf32(acc[nf], a0, a1, a2, a3, b0, b1);
            }
        }
        __syncthreads();
    }

    int row = m0 + wm * 16 + (lane >> 2);
    #pragma unroll
    for (int nf = 0; nf < 4; nf++) {
        int cg = n0 + wn * 32 + nf * 8 + (lane & 3) * 2;
        float bv0 = is_dec ? b1[cg]     : 0.0f;
        float bv1 = is_dec ? b1[cg + 1] : 0.0f;
        out[(size_t)row * H_ + cg]           = acc[nf][0] + bv0;
        out[(size_t)row * H_ + cg + 1]       = acc[nf][1] + bv1;
        out[(size_t)(row + 8) * H_ + cg]     = acc[nf][2] + bv0;
        out[(size_t)(row + 8) * H_ + cg + 1] = acc[nf][3] + bv1;
    }
}

// ---------------------------------------------------------------------------
// gemm_fused: M=64 tiles (one bt each), grid 1024, 256 threads, 2 CTAs/SM.
// Warp layout 2(m:32) x 4(n:32); acc = 32 regs. f32-acc m16n8k16.
// B is chunk-linear: chunk j = g_w2p + j*512 (8KB). Pair = 1024 uint4.
// 3-stage-pair cp.async pipeline, one barrier per pair. Modulo-free stage
// counters; prefetch source is a single advancing pointer.
// SMEM: A [0,65536), B pairs at 65536 + sp*16384, sp=0..2 => 114688 B.
// ---------------------------------------------------------------------------
#define FA_BYTES  65536
#define FBP_BYTES 16384                       // one stage-pair (2 x 8KB)
#define SMEM_F    (FA_BYTES + 3 * FBP_BYTES)  // 114688

__global__ __launch_bounds__(256, 2) void gemm_fused(float* __restrict__ out)
{
    extern __shared__ char smem[];
    const uint32_t sbase = smem_u32(smem);
    const int tid  = threadIdx.x;
    const int lane = tid & 31;
    const int w    = tid >> 5;
    const int wm   = w >> 2;          // 0..1 (32 rows each)
    const int wn   = w & 3;           // 0..3 (32 cols each)
    const int mt   = blockIdx.x;      // 0..1023 (= bt)

    // ---- prologue: prefetch pairs 0,1 (chunks 0..3), one commit per pair ----
    {
        const uint4* src = g_w2p + tid;
        uint32_t dst = sbase + FA_BYTES + tid * 16;
        #pragma unroll
        for (int pp = 0; pp < 2; pp++) {
            cp16(dst, src);
            cp16(dst + 4096,  src + 256);
            cp16(dst + 8192,  src + 512);
            cp16(dst + 12288, src + 768);
            cp_commit();
            src += 1024;
            dst += FBP_BYTES;
        }
    }

    // ---- Phase 1: A = gelu(enc+dec), fp16 fragment order, 64 rows ----
    {
        const int l    = tid & 31;
        const int mb2  = (tid >> 5) & 3;         // 16-row group 0..3
        const int half = tid >> 7;               // ch split 0..7 / 8..15
        const int rl   = mb2 * 16 + (l >> 2);    // row in tile = u
        const int bat  = mt >> 8;
        const float* ep  = g_enc + (size_t)mt * H_;
        const float* dp0 = g_dec + (size_t)(bat * 64 + rl) * H_;
        const float* dp1 = dp0 + 8 * H_;
        uint4* sA = (uint4*)smem;

        #pragma unroll 2
        for (int cho = 0; cho < 8; cho++) {
            const int ch = half * 8 + cho;
            #pragma unroll
            for (int ks = 0; ks < 2; ks++) {
                int cb = ch * 32 + ks * 16 + (l & 3) * 2;
                float2 e0 = *(const float2*)(ep + cb);
                float2 e1 = *(const float2*)(ep + cb + 8);
                float2 a0 = *(const float2*)(dp0 + cb);
                float2 a1 = *(const float2*)(dp0 + cb + 8);
                float2 c0 = *(const float2*)(dp1 + cb);
                float2 c1 = *(const float2*)(dp1 + cb + 8);
                uint4 q;
                q.x = packh2(gelu_tanh(e0.x + a0.x), gelu_tanh(e0.y + a0.y));
                q.y = packh2(gelu_tanh(e0.x + c0.x), gelu_tanh(e0.y + c0.y));
                q.z = packh2(gelu_tanh(e1.x + a1.x), gelu_tanh(e1.y + a1.y));
                q.w = packh2(gelu_tanh(e1.x + c1.x), gelu_tanh(e1.y + c1.y));
                sA[(ch * 8 + mb2 * 2 + ks) * 32 + l] = q;
            }
        }
    }

    // ---- Phase 2: 64 chunk-pairs, one barrier per pair ----
    const size_t rbase = (size_t)mt * 64;
    float acc[2][4][4] = {};

    // modulo-free stage counters
    int sp  = 0;                       // stage-pair to consume this iteration
    int spw = 2;                       // stage-pair to write (prefetch) into
    const uint4* srcPf = g_w2p + 4 * 512 + tid;   // chunk 4 onward
    // per-thread smem read bases (hoisted)
    const uint32_t aBase = sbase;                 // + ch*4096 per chunk
    const uint32_t bBase = sbase + FA_BYTES;      // + (sp*2+cc)*8192

    for (int jp = 0; jp < 64; jp++) {
        cp_wait<1>();        // pair jp landed (pair jp+1 in flight)
        __syncthreads();     // also covers A availability on jp==0

        if (jp < 62) {       // prefetch pair jp+2 into freed stage-pair
            uint32_t dst = bBase + spw * FBP_BYTES + tid * 16;
            cp16(dst,         srcPf);
            cp16(dst + 4096,  srcPf + 256);
            cp16(dst + 8192,  srcPf + 512);
            cp16(dst + 12288, srcPf + 768);
            srcPf += 1024;
        }
        cp_commit();
        spw = (spw == 2) ? 0 : spw + 1;

        #pragma unroll
        for (int cc = 0; cc < 2; cc++) {
            const int ch = (2 * jp + cc) & 15;
            const uint4* sA = (const uint4*)(smem + ch * 4096);
            const uint4* sB = (const uint4*)(smem + FA_BYTES +
                                             (sp * 2 + cc) * 8192);

            uint4 bf[4];
            #pragma unroll
            for (int p = 0; p < 4; p++)
                bf[p] = sB[(wn * 4 + p) * 32 + lane];

            #pragma unroll
            for (int ks = 0; ks < 2; ks++) {
                uint4 af[2];
                #pragma unroll
                for (int mb = 0; mb < 2; mb++)
                    af[mb] = sA[((wm * 2 + mb) * 2 + ks) * 32 + lane];
                #pragma unroll
                for (int mb = 0; mb < 2; mb++) {
                    #pragma unroll
                    for (int p = 0; p < 4; p++) {
                        uint32_t b0 = ks ? bf[p].z : bf[p].x;
                        uint32_t b1 = ks ? bf[p].w : bf[p].y;
                        mma_f16(acc[mb][p], af[mb].x, af[mb].y, af[mb].z,
                                af[mb].w, b0, b1);
                    }
                }
            }
        }
        sp = (sp == 2) ? 0 : sp + 1;

        // epilogue after each 8-pair group (one nt8 of 128 columns)
        if ((jp & 7) == 7) {
            const int nt8 = jp >> 3;
            #pragma unroll
            for (int mb = 0; mb < 2; mb++) {
                size_t r = rbase + wm * 32 + mb * 16 + (lane >> 2);
                #pragma unroll
                for (int p = 0; p < 4; p++) {
                    int cg = nt8 * 128 + wn * 32 + p * 8 + (lane & 3) * 2;
                    *(float2*)(out + r * V_ + cg) =
                        make_float2(acc[mb][p][0], acc[mb][p][1]);
                    *(float2*)(out + (r + 8) * V_ + cg) =
                        make_float2(acc[mb][p][2], acc[mb][p][3]);
                    acc[mb][p][0] = 0.0f; acc[mb][p][1] = 0.0f;
                    acc[mb][p][2] = 0.0f; acc[mb][p][3] = 0.0f;
                }
            }
        }
    }
}

extern "C" void kernel_launch(void* const* d_in, const int* in_sizes, int n_in,
                              void* d_out, int out_size) {
    const float* enc = (const float*)d_in[0];
    const float* dec = (const float*)d_in[1];
    const float* w1  = (const float*)d_in[2];
    const float* b1  = (const float*)d_in[3];
    const float* w2  = (const float*)d_in[4];
    float* out = (float*)d_out;

    cudaFuncSetAttribute(prep_kernel, cudaFuncAttributeMaxDynamicSharedMemorySize, P_SMEM);
    cudaFuncSetAttribute(gemm_fused, cudaFuncAttributeMaxDynamicSharedMemorySize, SMEM_F);
    prep_kernel<<<416, 256, P_SMEM>>>(enc, dec, w1, b1, w2);
    gemm_fused<<<1024, 256, SMEM_F>>>(out);
}

// round 17
// speedup vs baseline: 2.2727x; 1.0636x over previous
#include <cuda_runtime.h>
#include <cuda_fp16.h>
#include <cstdint>

#define B_ 4
#define T_ 256
#define U_ 64
#define D_ 512
#define H_ 512
#define V_ 1024

// ---------------------------------------------------------------------------
// Device-global scratch (allocation-free rule)
// ---------------------------------------------------------------------------
__device__ float g_enc[B_ * T_ * H_];          // 1024 x 512 enc_proj (fp32)
__device__ float g_dec[B_ * U_ * H_];          // 256  x 512 dec_proj + b1 (fp32)
__device__ uint4 g_w2p[128 * 512];             // w2 fp16, ch-major pair packed (1 MB)

__device__ __forceinline__ uint32_t f2tf32(float x) {
    uint32_t u; asm("cvt.rna.tf32.f32 %0, %1;" : "=r"(u) : "f"(x)); return u;
}
__device__ __forceinline__ uint32_t packh2(float a, float b) {
    __half2 h = __floats2half2_rn(a, b);
    return *reinterpret_cast<uint32_t*>(&h);
}
__device__ __forceinline__ float gelu_tanh(float x) {
    float t = 0.7978845608028654f * (x + 0.044715f * x * x * x);
    float th; asm("tanh.approx.f32 %0, %1;" : "=f"(th) : "f"(t));
    return 0.5f * x * (1.0f + th);
}
__device__ __forceinline__ uint32_t smem_u32(const void* p) {
    uint32_t a;
    asm("{ .reg .u64 t; cvta.to.shared.u64 t, %1; cvt.u32.u64 %0, t; }" : "=r"(a) : "l"(p));
    return a;
}
__device__ __forceinline__ void mma_tf32(float* acc, uint32_t a0, uint32_t a1,
                                         uint32_t a2, uint32_t a3,
                                         uint32_t b0, uint32_t b1) {
    asm volatile(
        "mma.sync.aligned.m16n8k8.row.col.f32.tf32.tf32.f32 "
        "{%0,%1,%2,%3}, {%4,%5,%6,%7}, {%8,%9}, {%0,%1,%2,%3};"
        : "+f"(acc[0]), "+f"(acc[1]), "+f"(acc[2]), "+f"(acc[3])
        : "r"(a0), "r"(a1), "r"(a2), "r"(a3), "r"(b0), "r"(b1));
}
__device__ __forceinline__ void mma_f16(float* acc, uint32_t a0, uint32_t a1,
                                        uint32_t a2, uint32_t a3,
                                        uint32_t b0, uint32_t b1) {
    asm volatile(
        "mma.sync.aligned.m16n8k16.row.col.f32.f16.f16.f32 "
        "{%0,%1,%2,%3}, {%4,%5,%6,%7}, {%8,%9}, {%0,%1,%2,%3};"
        : "+f"(acc[0]), "+f"(acc[1]), "+f"(acc[2]), "+f"(acc[3])
        : "r"(a0), "r"(a1), "r"(a2), "r"(a3), "r"(b0), "r"(b1));
}
__device__ __forceinline__ void cp16(uint32_t sdst, const void* gsrc) {
    asm volatile("cp.async.cg.shared.global [%0], [%1], 16;" :: "r"(sdst), "l"(gsrc));
}
__device__ __forceinline__ void cp_commit() {
    asm volatile("cp.async.commit_group;" ::: "memory");
}
template <int N>
__device__ __forceinline__ void cp_wait() {
    asm volatile("cp.async.wait_group %0;" :: "n"(N) : "memory");
}

// ---------------------------------------------------------------------------
// prep_kernel:
//   blocks 0..159  : enc/dec projections (tf32 mma, M=32 N=128, K=64 chunks)
//   blocks 160..415: w2 -> g_w2p fp16 pack, CH-MAJOR PAIR order:
//     slot j = np*32 + ch*2 + h  (np = 256-col pair group 0..3, ch = k32
//     group 0..15, h = nt8 half 0..1, nt8 = np*2+h). Chunk j occupies
//     g_w2p[j*512 .. j*512+512). Within: slot (p8, l):
//       n  = (np*2+h)*128 + p8*8 + (l>>2)   (output column / w2 row)
//       c0 = ch*32 + (l&3)*2                (k position)
//       uint4 = {h2(n,c0), h2(n,c0+8), h2(n,c0+16), h2(n,c0+24)}
// ---------------------------------------------------------------------------
#define PA_STRIDE 272
#define PB_STRIDE 272
#define P_OFF_A   0
#define P_OFF_B   17408
#define P_SMEM    87040

__global__ __launch_bounds__(256) void prep_kernel(
    const float* __restrict__ enc, const float* __restrict__ dec,
    const float* __restrict__ w1, const float* __restrict__ b1,
    const float* __restrict__ w2)
{
    const int bid = blockIdx.x;
    const int tid = threadIdx.x;

    if (bid >= 160) {   // ---- w2 fp16 pack, ch-major pair order ----
        int t   = (bid - 160) * 256 + tid;      // 0..65535
        int l   = t & 31;
        int p8  = (t >> 5) & 15;
        int j   = t >> 9;                       // 0..127
        int h   = j & 1;
        int ch  = (j >> 1) & 15;
        int np  = j >> 5;
        int n   = (np * 2 + h) * 128 + p8 * 8 + (l >> 2);
        int c0  = ch * 32 + (l & 3) * 2;
        const float* r = w2 + (size_t)n * H_;
        float2 v0 = *(const float2*)(r + c0);
        float2 v1 = *(const float2*)(r + c0 + 8);
        float2 v2 = *(const float2*)(r + c0 + 16);
        float2 v3 = *(const float2*)(r + c0 + 24);
        uint4 q;
        q.x = packh2(v0.x, v0.y);
        q.y = packh2(v1.x, v1.y);
        q.z = packh2(v2.x, v2.y);
        q.w = packh2(v3.x, v3.y);
        g_w2p[((size_t)j * 16 + p8) * 32 + l] = q;
        return;
    }

    extern __shared__ char psm[];
    const uint32_t sbase = smem_u32(psm);

    const int ng = bid & 3;
    const int my = bid >> 2;
    const bool is_dec = (my >= 32);
    const float* A = is_dec ? dec : enc;
    const float* W = is_dec ? (w1 + D_) : w1;
    float* out     = is_dec ? g_dec : g_enc;
    const int m0   = (is_dec ? (my - 32) : my) * 32;
    const int n0   = ng * 128;

    const int lane = tid & 31;
    const int w    = tid >> 5;
    const int wm   = w >> 2;
    const int wn   = w & 3;
    float acc[4][4] = {};

    {
        if (tid < 128) {
            int j = tid;
            #pragma unroll
            for (int i = 0; i < 4; i++, j += 128) {
                int r = j >> 4, seg = j & 15;
                cp16(sbase + P_OFF_A + r * PA_STRIDE + seg * 16,
                     A + (size_t)(m0 + r) * D_ + seg * 4);
            }
        }
        int j = tid;
        #pragma unroll
        for (int i = 0; i < 8; i++, j += 256) {
            int r = j >> 4, seg = j & 15;
            cp16(sbase + P_OFF_B + r * PB_STRIDE + seg * 16,
                 W + (size_t)(n0 + r) * (2 * D_) + seg * 4);
        }
        cp_commit();
    }

    for (int cc = 0; cc < 8; cc++) {
        const int s = cc & 1;
        if (cc < 7) {
            const int sn = s ^ 1;
            const int k0 = (cc + 1) * 64;
            if (tid < 128) {
                int j = tid;
                #pragma unroll
                for (int i = 0; i < 4; i++, j += 128) {
                    int r = j >> 4, seg = j & 15;
                    cp16(sbase + P_OFF_A + sn * 8704 + r * PA_STRIDE + seg * 16,
                         A + (size_t)(m0 + r) * D_ + k0 + seg * 4);
                }
            }
            int j = tid;
            #pragma unroll
            for (int i = 0; i < 8; i++, j += 256) {
                int r = j >> 4, seg = j & 15;
                cp16(sbase + P_OFF_B + sn * 34816 + r * PB_STRIDE + seg * 16,
                     W + (size_t)(n0 + r) * (2 * D_) + k0 + seg * 4);
            }
            cp_commit();
            cp_wait<1>();
        } else {
            cp_wait<0>();
        }
        __syncthreads();

        const float* Af = (const float*)(psm + P_OFF_A + s * 8704);
        const float* Bf = (const float*)(psm + P_OFF_B + s * 34816);

        #pragma unroll
        for (int kk = 0; kk < 8; kk++) {
            int ar = wm * 16 + (lane >> 2);
            int ac = kk * 8 + (lane & 3);
            uint32_t a0 = f2tf32(Af[ar * 68 + ac]);
            uint32_t a1 = f2tf32(Af[(ar + 8) * 68 + ac]);
            uint32_t a2 = f2tf32(Af[ar * 68 + ac + 4]);
            uint32_t a3 = f2tf32(Af[(ar + 8) * 68 + ac + 4]);
            #pragma unroll
            for (int nf = 0; nf < 4; nf++) {
                int br = wn * 32 + nf * 8 + (lane >> 2);
                uint32_t b0 = f2tf32(Bf[br * 68 + ac]);
                uint32_t b1 = f2tf32(Bf[br * 68 + ac + 4]);
                mma_tf32(acc[nf], a0, a1, a2, a3, b0, b1);
            }
        }
        __syncthreads();
    }

    int row = m0 + wm * 16 + (lane >> 2);
    #pragma unroll
    for (int nf = 0; nf < 4; nf++) {
        int cg = n0 + wn * 32 + nf * 8 + (lane & 3) * 2;
        float bv0 = is_dec ? b1[cg]     : 0.0f;
        float bv1 = is_dec ? b1[cg + 1] : 0.0f;
        out[(size_t)row * H_ + cg]           = acc[nf][0] + bv0;
        out[(size_t)row * H_ + cg + 1]       = acc[nf][1] + bv1;
        out[(size_t)(row + 8) * H_ + cg]     = acc[nf][2] + bv0;
        out[(size_t)(row + 8) * H_ + cg + 1] = acc[nf][3] + bv1;
    }
}

// ---------------------------------------------------------------------------
// gemm_fused: M=64 tiles (one bt each), grid 1024, 256 threads, 2 CTAs/SM.
// Warp layout 2(m:32) x 4(n:32), TWO nt8 halves live => warp output 32x64,
// acc = 64 regs. f32-acc m16n8k16.
// B is ch-major pair packed: pair jp = {chunks 2jp, 2jp+1} = same k-chunk
// (ch = jp & 15) for two adjacent nt8 groups => A frags loaded ONCE per pair.
// 3-stage-pair cp.async pipeline, one barrier per pair, modulo-free counters.
// SMEM: A [0,65536), B pairs at 65536 + sp*16384, sp=0..2 => 114688 B.
// ---------------------------------------------------------------------------
#define FA_BYTES  65536
#define FBP_BYTES 16384                       // one stage-pair (2 x 8KB)
#define SMEM_F    (FA_BYTES + 3 * FBP_BYTES)  // 114688

__global__ __launch_bounds__(256, 2) void gemm_fused(float* __restrict__ out)
{
    extern __shared__ char smem[];
    const uint32_t sbase = smem_u32(smem);
    const int tid  = threadIdx.x;
    const int lane = tid & 31;
    const int w    = tid >> 5;
    const int wm   = w >> 2;          // 0..1 (32 rows each)
    const int wn   = w & 3;           // 0..3 (32 cols each per half)
    const int mt   = blockIdx.x;      // 0..1023 (= bt)

    // ---- prologue: prefetch pairs 0,1 (chunks 0..3), one commit per pair ----
    {
        const uint4* src = g_w2p + tid;
        uint32_t dst = sbase + FA_BYTES + tid * 16;
        #pragma unroll
        for (int pp = 0; pp < 2; pp++) {
            cp16(dst, src);
            cp16(dst + 4096,  src + 256);
            cp16(dst + 8192,  src + 512);
            cp16(dst + 12288, src + 768);
            cp_commit();
            src += 1024;
            dst += FBP_BYTES;
        }
    }

    // ---- Phase 1: A = gelu(enc+dec), fp16 fragment order, 64 rows ----
    {
        const int l    = tid & 31;
        const int mb2  = (tid >> 5) & 3;         // 16-row group 0..3
        const int half = tid >> 7;               // ch split 0..7 / 8..15
        const int rl   = mb2 * 16 + (l >> 2);    // row in tile = u
        const int bat  = mt >> 8;
        const float* ep  = g_enc + (size_t)mt * H_;
        const float* dp0 = g_dec + (size_t)(bat * 64 + rl) * H_;
        const float* dp1 = dp0 + 8 * H_;
        uint4* sA = (uint4*)smem;

        #pragma unroll 2
        for (int cho = 0; cho < 8; cho++) {
            const int ch = half * 8 + cho;
            #pragma unroll
            for (int ks = 0; ks < 2; ks++) {
                int cb = ch * 32 + ks * 16 + (l & 3) * 2;
                float2 e0 = *(const float2*)(ep + cb);
                float2 e1 = *(const float2*)(ep + cb + 8);
                float2 a0 = *(const float2*)(dp0 + cb);
                float2 a1 = *(const float2*)(dp0 + cb + 8);
                float2 c0 = *(const float2*)(dp1 + cb);
                float2 c1 = *(const float2*)(dp1 + cb + 8);
                uint4 q;
                q.x = packh2(gelu_tanh(e0.x + a0.x), gelu_tanh(e0.y + a0.y));
                q.y = packh2(gelu_tanh(e0.x + c0.x), gelu_tanh(e0.y + c0.y));
                q.z = packh2(gelu_tanh(e1.x + a1.x), gelu_tanh(e1.y + a1.y));
                q.w = packh2(gelu_tanh(e1.x + c1.x), gelu_tanh(e1.y + c1.y));
                sA[(ch * 8 + mb2 * 2 + ks) * 32 + l] = q;
            }
        }
    }

    // ---- Phase 2: 64 ch-major pairs, one barrier per pair ----
    const size_t rbase = (size_t)mt * 64;
    float acc[2][2][4][4] = {};       // [h][mb][p][4] -> 64 regs

    int sp  = 0;                       // stage-pair to consume
    int spw = 2;                       // stage-pair to prefetch into
    const uint4* srcPf = g_w2p + 4 * 512 + tid;   // chunk 4 onward (linear)
    const uint32_t bBase = sbase + FA_BYTES;

    for (int jp = 0; jp < 64; jp++) {
        cp_wait<1>();        // pair jp landed (pair jp+1 in flight)
        __syncthreads();     // also covers A availability on jp==0

        if (jp < 62) {       // prefetch pair jp+2 into freed stage-pair
            uint32_t dst = bBase + spw * FBP_BYTES + tid * 16;
            cp16(dst,         srcPf);
            cp16(dst + 4096,  srcPf + 256);
            cp16(dst + 8192,  srcPf + 512);
            cp16(dst + 12288, srcPf + 768);
            srcPf += 1024;
        }
        cp_commit();
        spw = (spw == 2) ? 0 : spw + 1;

        const int ch = jp & 15;
        const uint4* sA = (const uint4*)(smem + ch * 4096);

        // A fragments: loaded ONCE for both halves of the pair
        uint4 af[2][2];   // [mb][ks]
        #pragma unroll
        for (int mb = 0; mb < 2; mb++)
            #pragma unroll
            for (int ks = 0; ks < 2; ks++)
                af[mb][ks] = sA[((wm * 2 + mb) * 2 + ks) * 32 + lane];

        #pragma unroll
        for (int h = 0; h < 2; h++) {
            const uint4* sB = (const uint4*)(smem + FA_BYTES +
                                             (sp * 2 + h) * 8192);
            uint4 bf[4];
            #pragma unroll
            for (int p = 0; p < 4; p++)
                bf[p] = sB[(wn * 4 + p) * 32 + lane];

            #pragma unroll
            for (int ks = 0; ks < 2; ks++) {
                #pragma unroll
                for (int mb = 0; mb < 2; mb++) {
                    #pragma unroll
                    for (int p = 0; p < 4; p++) {
                        uint32_t b0 = ks ? bf[p].z : bf[p].x;
                        uint32_t b1 = ks ? bf[p].w : bf[p].y;
                        mma_f16(acc[h][mb][p], af[mb][ks].x, af[mb][ks].y,
                                af[mb][ks].z, af[mb][ks].w, b0, b1);
                    }
                }
            }
        }
        sp = (sp == 2) ? 0 : sp + 1;

        // epilogue after each 16-pair group (one np of 256 columns)
        if ((jp & 15) == 15) {
            const int np = jp >> 4;
            #pragma unroll
            for (int h = 0; h < 2; h++) {
                #pragma unroll
                for (int mb = 0; mb < 2; mb++) {
                    size_t r = rbase + wm * 32 + mb * 16 + (lane >> 2);
                    #pragma unroll
                    for (int p = 0; p < 4; p++) {
                        int cg = np * 256 + h * 128 + wn * 32 + p * 8 +
                                 (lane & 3) * 2;
                        *(float2*)(out + r * V_ + cg) =
                            make_float2(acc[h][mb][p][0], acc[h][mb][p][1]);
                        *(float2*)(out + (r + 8) * V_ + cg) =
                            make_float2(acc[h][mb][p][2], acc[h][mb][p][3]);
                        acc[h][mb][p][0] = 0.0f; acc[h][mb][p][1] = 0.0f;
                        acc[h][mb][p][2] = 0.0f; acc[h][mb][p][3] = 0.0f;
                    }
                }
            }
        }
    }
}

extern "C" void kernel_launch(void* const* d_in, const int* in_sizes, int n_in,
                              void* d_out, int out_size) {
    const float* enc = (const float*)d_in[0];
    const float* dec = (const float*)d_in[1];
    const float* w1  = (const float*)d_in[2];
    const float* b1  = (const float*)d_in[3];
    const float* w2  = (const float*)d_in[4];
    float* out = (float*)d_out;

    cudaFuncSetAttribute(prep_kernel, cudaFuncAttributeMaxDynamicSharedMemorySize, P_SMEM);
    cudaFuncSetAttribute(gemm_fused, cudaFuncAttributeMaxDynamicSharedMemorySize, SMEM_F);
    prep_kernel<<<416, 256, P_SMEM>>>(enc, dec, w1, b1, w2);
    gemm_fused<<<1024, 256, SMEM_F>>>(out);
}